// round 17
// baseline (speedup 1.0000x reference)
#include <cuda_runtime.h>
#include <cuda_fp16.h>
#include <cstdint>

#define H        64
#define NPIX     65536
#define LBATCH   8
#define NSPLIT   37                      // 8*37 = 296 CTAs = 148 SMs * 2 CTAs (1 wave)
#define NCTA     (LBATCH * NSPLIT)
#define NCHUNKS  512                     // 128-pixel chunks per image

// scratch: per-CTA 3 GEMM tiles: [cta][gemm][64*64]
__device__ float g_part[(size_t)NCTA * 3 * H * H];
// per-CTA total mass (sum of all 3 tiles) for fused normalization
__device__ float g_psum[NCTA];

#define BUF_BYTES 0xC000u                      // 3*8*4*32 uint4 = 48 KB per buffer
#define SMEM_BYTES (2 * BUF_BYTES)             // 96 KB

__device__ __forceinline__ uint32_t smem_u32(const void* p) {
    uint32_t a;
    asm("{ .reg .u64 t; cvta.to.shared.u64 t, %1; cvt.u32.u64 %0, t; }" : "=r"(a) : "l"(p));
    return a;
}
__device__ __forceinline__ unsigned pk(float lo, float hi) {  // f32x2 -> f16x2
    unsigned r; asm("cvt.rn.f16x2.f32 %0, %2, %1;" : "=r"(r) : "f"(lo), "f"(hi));
    return r;
}
__device__ __forceinline__ unsigned hm2(unsigned a, unsigned b) {
    unsigned r; asm("mul.rn.f16x2 %0, %1, %2;" : "=r"(r) : "r"(a), "r"(b));
    return r;
}
__device__ __forceinline__ float lg2a(float x) {
    float r; asm("lg2.approx.f32 %0, %1;" : "=f"(r) : "f"(x));
    return r;
}
__device__ __forceinline__ float sqrta(float x) {
    float r; asm("sqrt.approx.f32 %0, %1;" : "=f"(r) : "f"(x));
    return r;
}
__device__ __forceinline__ float rcpa(float x) {
    float r; asm("rcp.approx.ftz.f32 %0, %1;" : "=f"(r) : "f"(x));
    return r;
}
// two kernel values (pixels u0,u1 at same bin), sqrt-weight folded, via the
// product-reciprocal trick: ONE f32 MUFU per pair, f32 math until final pack.
__device__ __forceinline__ unsigned kv(float u0, float u1, unsigned sw2) {
    float a = fmaf(u0, u0, 1.0f);
    float b = fmaf(u1, u1, 1.0f);
    float r = rcpa(a * b);
    return hm2(pk(b * r, a * r), sw2);
}
__device__ __forceinline__ void mma16816(float* c, const unsigned* a, unsigned b0, unsigned b1) {
    asm volatile(
        "mma.sync.aligned.m16n8k16.row.col.f32.f16.f16.f32 "
        "{%0,%1,%2,%3}, {%4,%5,%6,%7}, {%8,%9}, {%0,%1,%2,%3};"
        : "+f"(c[0]), "+f"(c[1]), "+f"(c[2]), "+f"(c[3])
        : "r"(a[0]), "r"(a[1]), "r"(a[2]), "r"(a[3]), "r"(b0), "r"(b1));
}
__device__ __forceinline__ float shf(float v, int src) {
    return __shfl_sync(0xffffffffu, v, src);
}
__device__ __forceinline__ uint4 lds128(uint32_t a) {
    uint4 v;
    asm volatile("ld.shared.v4.b32 {%0,%1,%2,%3}, [%4];"
                 : "=r"(v.x), "=r"(v.y), "=r"(v.z), "=r"(v.w) : "r"(a));
    return v;
}
__device__ __forceinline__ void sts128(uint32_t a, uint4 v) {
    asm volatile("st.shared.v4.b32 [%0], {%1,%2,%3,%4};"
                 :: "r"(a), "r"(v.x), "r"(v.y), "r"(v.z), "r"(v.w) : "memory");
}

// 12 warps per CTA. Warp w: g = w%3 (vector/GEMM id), h = w/3 in 0..3.
// 128-px chunks, software-pipelined: region r = [interleaved consume(chunk r,
// buf r&1) + prep/produce(chunk r+1, buf (r&1)^1)], one barrier per region.
// Buffer layout (bytes, per buffer): ((vec*8+st)*4+m)*512 + L*16.
__global__ __launch_bounds__(384, 2) void hist_main(const float* __restrict__ x) {
    extern __shared__ uint4 img[];

    const int tid = threadIdx.x;
    const int w = tid >> 5;
    const int L = tid & 31;
    const int g = w % 3, h = w / 3;
    const int mi = h >> 1, ni = h & 1;
    const int bx = blockIdx.x;
    const int l = bx / NSPLIT, split = bx % NSPLIT;
    const int cbeg = (split * NCHUNKS) / NSPLIT;
    const int cend = ((split + 1) * NCHUNKS) / NSPLIT;
    const float* __restrict__ xp = x + (size_t)l * 3 * NPIX + 32 * h + L;

    const uint32_t sb = smem_u32(img);
    const int aimg = g >> 1;                  // A-operand image per GEMM
    const int bimg = (g == 0) ? 1 : 2;        // B-operand image per GEMM
    uint32_t baseA = sb + (uint32_t)aimg * 16384 + (uint32_t)mi * 1024 + (uint32_t)L * 16;
    uint32_t baseB = sb + (uint32_t)bimg * 16384 + (uint32_t)ni * 1024 + (uint32_t)L * 16;
    uint32_t baseP = sb + (uint32_t)g * 16384 + (uint32_t)(2 * h) * 2048 + (uint32_t)L * 16;

    float acc[2][4][4];
#pragma unroll
    for (int m = 0; m < 2; m++)
#pragma unroll
        for (int j = 0; j < 4; j++)
#pragma unroll
            for (int k = 0; k < 4; k++) acc[m][j][k] = 0.0f;

    const float DLT = (6.0f / 63.0f) * 50.0f;             // scaled bin spacing
    const int q = L & 3;
    const float SC = 34.65735903f;            // ln(2)/sigma
    // hoisted bin-offset pairs per m-block: oo[2m]=o0(m), oo[2m+1]=o1(m)
    float oo[8];
#pragma unroll
    for (int m = 0; m < 8; m++)
        oo[m] = -150.0f + (float)((L >> 2) + 8 * m) * DLT;

    // prefetch first chunk (all 3 channels of this warp's 32 pixels)
    float pi0 = xp[(size_t)cbeg * 128];
    float pi1 = xp[(size_t)cbeg * 128 + NPIX];
    float pi2 = xp[(size_t)cbeg * 128 + 2 * NPIX];

    float pd[8];        // fragment-ordered d values, [si][4]
    unsigned ps[4];     // fragment-ordered packed sqrt-weights, [si][2]

    auto prep = [&](int ch) {
        float i0 = fminf(fmaxf(pi0, 0.0f), 1.0f);
        float i1 = fminf(fmaxf(pi1, 0.0f), 1.0f);
        float i2 = fminf(fmaxf(pi2, 0.0f), 1.0f);
        if (ch + 1 < cend) {
            pi0 = xp[(size_t)(ch + 1) * 128];
            pi1 = xp[(size_t)(ch + 1) * 128 + NPIX];
            pi2 = xp[(size_t)(ch + 1) * 128 + 2 * NPIX];
        }
        float l0 = lg2a(i0 + 1e-6f);
        float l1 = lg2a(i1 + 1e-6f);
        float l2 = lg2a(i2 + 1e-6f);
        float d = (g == 0) ? (l0 - l1) : (g == 1) ? (l0 - l2) : (l1 - l2);
        d *= SC;
        float s = fmaf(i0, i0, fmaf(i1, i1, fmaf(i2, i2, 1e-6f)));
        float sw = sqrta(sqrta(s));           // sqrt(Iy)
#pragma unroll
        for (int si = 0; si < 2; si++) {
            const int b0 = 16 * si + 2 * q;
            pd[4 * si + 0] = shf(d, b0);
            pd[4 * si + 1] = shf(d, b0 + 1);
            pd[4 * si + 2] = shf(d, b0 + 8);
            pd[4 * si + 3] = shf(d, b0 + 9);
            ps[2 * si + 0] = pk(shf(sw, b0),     shf(sw, b0 + 1));
            ps[2 * si + 1] = pk(shf(sw, b0 + 8), shf(sw, b0 + 9));
        }
    };

    const int nreg = cend - cbeg;
    // prologue: produce chunk cbeg into buf 0
    prep(cbeg);
#pragma unroll
    for (int k = 0; k < 8; k++) {
        const int si = k >> 2, m = k & 3;
        const float o0 = oo[2 * m], o1 = oo[2 * m + 1];
        uint4 v;
        v.x = kv(pd[4 * si + 0] - o0, pd[4 * si + 1] - o0, ps[2 * si]);
        v.y = kv(pd[4 * si + 0] - o1, pd[4 * si + 1] - o1, ps[2 * si]);
        v.z = kv(pd[4 * si + 2] - o0, pd[4 * si + 3] - o0, ps[2 * si + 1]);
        v.w = kv(pd[4 * si + 2] - o1, pd[4 * si + 3] - o1, ps[2 * si + 1]);
        sts128(baseP + (uint32_t)(si * 2048 + m * 512), v);
    }
    __syncthreads();

    int32_t pDelta = BUF_BYTES, cDelta = BUF_BYTES;
#pragma unroll 1
    for (int r = 0; r < nreg - 1; r++) {
        baseP += pDelta; pDelta = -pDelta;    // produce -> other buffer
        prep(cbeg + r + 1);
#pragma unroll
        for (int k = 0; k < 8; k++) {
            // consume K-step k from current buffer (immediate offsets)
            uint4 A0 = lds128(baseA + (uint32_t)(k * 2048));
            uint4 A1 = lds128(baseA + (uint32_t)(k * 2048 + 512));
            uint4 W0 = lds128(baseB + (uint32_t)(k * 2048));
            uint4 W1 = lds128(baseB + (uint32_t)(k * 2048 + 512));
            mma16816(acc[0][0], (const unsigned*)&A0, W0.x, W0.z);
            mma16816(acc[1][0], (const unsigned*)&A1, W0.x, W0.z);
            mma16816(acc[0][1], (const unsigned*)&A0, W0.y, W0.w);
            mma16816(acc[1][1], (const unsigned*)&A1, W0.y, W0.w);
            mma16816(acc[0][2], (const unsigned*)&A0, W1.x, W1.z);
            mma16816(acc[1][2], (const unsigned*)&A1, W1.x, W1.z);
            mma16816(acc[0][3], (const unsigned*)&A0, W1.y, W1.w);
            mma16816(acc[1][3], (const unsigned*)&A1, W1.y, W1.w);
            // produce block k of next chunk into the other buffer
            const int si = k >> 2, m = k & 3;
            const float o0 = oo[2 * m], o1 = oo[2 * m + 1];
            uint4 v;
            v.x = kv(pd[4 * si + 0] - o0, pd[4 * si + 1] - o0, ps[2 * si]);
            v.y = kv(pd[4 * si + 0] - o1, pd[4 * si + 1] - o1, ps[2 * si]);
            v.z = kv(pd[4 * si + 2] - o0, pd[4 * si + 3] - o0, ps[2 * si + 1]);
            v.w = kv(pd[4 * si + 2] - o1, pd[4 * si + 3] - o1, ps[2 * si + 1]);
            sts128(baseP + (uint32_t)(si * 2048 + m * 512), v);
        }
        __syncthreads();
        baseA += cDelta; baseB += cDelta; cDelta = -cDelta;
    }
    // final region: consume only
#pragma unroll
    for (int k = 0; k < 8; k++) {
        uint4 A0 = lds128(baseA + (uint32_t)(k * 2048));
        uint4 A1 = lds128(baseA + (uint32_t)(k * 2048 + 512));
        uint4 W0 = lds128(baseB + (uint32_t)(k * 2048));
        uint4 W1 = lds128(baseB + (uint32_t)(k * 2048 + 512));
        mma16816(acc[0][0], (const unsigned*)&A0, W0.x, W0.z);
        mma16816(acc[1][0], (const unsigned*)&A1, W0.x, W0.z);
        mma16816(acc[0][1], (const unsigned*)&A0, W0.y, W0.w);
        mma16816(acc[1][1], (const unsigned*)&A1, W0.y, W0.w);
        mma16816(acc[0][2], (const unsigned*)&A0, W1.x, W1.z);
        mma16816(acc[1][2], (const unsigned*)&A1, W1.x, W1.z);
        mma16816(acc[0][3], (const unsigned*)&A0, W1.y, W1.w);
        mma16816(acc[1][3], (const unsigned*)&A1, W1.y, W1.w);
    }

    // store this warp's 32x32 quadrant (non-atomic, private slot)
    float* dst = g_part + ((size_t)bx * 3 + g) * (H * H);
    const int r = L >> 2;
    const int qq = (L & 3) * 2;
#pragma unroll
    for (int m = 0; m < 2; m++)
#pragma unroll
        for (int jl = 0; jl < 4; jl++) {
            const int row0 = (2 * mi + m) * 16 + r;
            const int col = (4 * ni + jl) * 8 + qq;
            *(float2*)(dst + row0 * H + col)       = make_float2(acc[m][jl][0], acc[m][jl][1]);
            *(float2*)(dst + (row0 + 8) * H + col) = make_float2(acc[m][jl][2], acc[m][jl][3]);
        }

    // fused totals: per-warp sum of accs -> smem -> g_psum[bx]
    float wsum = 0.0f;
#pragma unroll
    for (int m = 0; m < 2; m++)
#pragma unroll
        for (int jl = 0; jl < 4; jl++)
            wsum += (acc[m][jl][0] + acc[m][jl][1]) + (acc[m][jl][2] + acc[m][jl][3]);
#pragma unroll
    for (int off = 16; off > 0; off >>= 1)
        wsum += __shfl_xor_sync(0xffffffffu, wsum, off);
    __syncthreads();                       // consumes of img are done; reuse as scratch
    float* sscr = (float*)img;
    if (L == 0) sscr[w] = wsum;
    __syncthreads();
    if (tid == 0) {
        float t = 0.0f;
#pragma unroll
        for (int k = 0; k < 12; k++) t += sscr[k];
        g_psum[bx] = t;
    }
}

// grid (8, 24), 256 threads, 2 outputs per thread (float2). Sums NSPLIT splits
// with the channel reversal mapping AND normalizes by the per-sample total in
// one pass. __launch_bounds__(256) lets ptxas keep all 37 float2 loads in
// flight (MLP = 37 x 8B per thread).
__global__ __launch_bounds__(256) void hist_reduce(float* __restrict__ out) {
    const int lc = blockIdx.y;
    const int c = lc % 3, lidx = lc / 3;
    const int e = (blockIdx.x * 256 + threadIdx.x) * 2;   // 0,2,..,4094
    const int u = e >> 6, v = e & 63;
    // float2-aligned source offset for the pair {e, e+1}
    int se;                 // byte-pair start; c==2 pair is reversed on load
    if (c == 0)      se = e;                        // [e, e+1]
    else if (c == 1) se = ((63 - u) << 6) | v;      // same u-row, [v, v+1]
    else             se = 4094 - e;                 // [4094-e, 4095-e] (swap)

    const float2* __restrict__ src = (const float2*)(
        g_part + ((size_t)(lidx * NSPLIT) * 3 + c) * (H * H) + se);

    // batch ALL loads first (front-batched LDG.64s, full MLP)
    float2 vals[NSPLIT];
#pragma unroll
    for (int sp = 0; sp < NSPLIT; sp++)
        vals[sp] = src[(size_t)sp * 3 * (H * H) / 2];

    // per-sample total from per-CTA partials (overlaps with vals latency)
    __shared__ float tshare[NSPLIT];
    if (threadIdx.x < NSPLIT)
        tshare[threadIdx.x] = g_psum[lidx * NSPLIT + threadIdx.x];
    __syncthreads();
    float tot = 1e-6f;
#pragma unroll
    for (int k = 0; k < NSPLIT; k++) tot += tshare[k];   // broadcast LDS
    const float inv = 1.0f / tot;

    // pairwise tree-sum per component
    float x0 = 0, x1 = 0, y0 = 0, y1 = 0;
#pragma unroll
    for (int sp = 0; sp + 2 <= NSPLIT; sp += 2) {
        x0 += vals[sp].x;     y0 += vals[sp].y;
        x1 += vals[sp + 1].x; y1 += vals[sp + 1].y;
    }
    x0 += vals[NSPLIT - 1].x; y0 += vals[NSPLIT - 1].y;   // NSPLIT odd
    float sx = x0 + x1, sy = y0 + y1;

    if (c == 2) { float t = sx; sx = sy; sy = t; }        // reversed pair
    *(float2*)(out + lc * (H * H) + e) = make_float2(sx * inv, sy * inv);
}

extern "C" void kernel_launch(void* const* d_in, const int* in_sizes, int n_in,
                              void* d_out, int out_size) {
    const float* x = (const float*)d_in[0];
    float* out = (float*)d_out;
    (void)in_sizes; (void)n_in; (void)out_size;

    cudaFuncSetAttribute(hist_main, cudaFuncAttributeMaxDynamicSharedMemorySize,
                         SMEM_BYTES);
    hist_main<<<NCTA, 384, SMEM_BYTES>>>(x);
    hist_reduce<<<dim3(8, 24), 256>>>(out);
}